// round 1
// baseline (speedup 1.0000x reference)
#include <cuda_runtime.h>
#include <math.h>

#define NN 50000
#define EE 800000
#define GG 256
#define EPSF 1e-5f

// ---------------- scratch (static device globals; allocation-free) ----------
__device__ __align__(256) float g_hw[NN * 128];    // h = x @ W
__device__ __align__(256) float g_agg[NN * 128];   // aggregated / activation
__device__ __align__(256) float g_dis[NN];         // deg -> deg^{-1/2}
__device__ __align__(256) float g_norm[EE];        // per-edge norm
__device__ __align__(256) float g_stats[128];      // BN sum / sumsq (max C=64)
__device__ __align__(256) float g_pool[GG * 128];
__device__ __align__(256) float g_cnt[GG];
__device__ __align__(256) float g_z[GG * 135];
__device__ __align__(256) float g_m1[GG * 128];
__device__ __align__(256) float g_m2[GG * 64];
__device__ __align__(256) float g_m3[GG * 32];

__device__ __forceinline__ float geluf(float x) {
    return 0.5f * x * (1.0f + erff(x * 0.70710678118654752f));
}

__device__ __forceinline__ void red_add_v4(float* addr, float a, float b, float c, float d) {
    asm volatile("red.global.add.v4.f32 [%0], {%1,%2,%3,%4};"
                 :: "l"(addr), "f"(a), "f"(b), "f"(c), "f"(d)
                 : "memory");
}

// ---------------- graph norm ------------------------------------------------
__global__ void k_deg(const int* __restrict__ ei) {
    int e = blockIdx.x * blockDim.x + threadIdx.x;
    if (e < EE) atomicAdd(&g_dis[ei[EE + e]], 1.0f);
}
__global__ void k_dis() {
    int n = blockIdx.x * blockDim.x + threadIdx.x;
    if (n < NN) g_dis[n] = rsqrtf(g_dis[n] + 1.0f);   // +1 self-loop, deg >= 1
}
__global__ void k_norm(const int* __restrict__ ei) {
    int e = blockIdx.x * blockDim.x + threadIdx.x;
    if (e < EE) g_norm[e] = g_dis[ei[e]] * g_dis[ei[EE + e]];
}

// ---------------- GCN layer pieces ------------------------------------------
__global__ void k_mm(const float* __restrict__ in, const float* __restrict__ W,
                     int Cin, int Cout) {
    int t = blockIdx.x * blockDim.x + threadIdx.x;
    if (t >= NN * Cout) return;
    int n = t / Cout, c = t - n * Cout;
    const float* row = in + n * Cin;
    float s = 0.f;
    #pragma unroll 4
    for (int i = 0; i < Cin; ++i) s = fmaf(row[i], W[i * Cout + c], s);
    g_hw[t] = s;
}

// agg = b + h * dis^2   (self-loop contribution folded in)
__global__ void k_init(const float* __restrict__ b, int Cout) {
    int t = blockIdx.x * blockDim.x + threadIdx.x;
    if (t >= NN * Cout) return;
    int n = t / Cout, c = t - n * Cout;
    float d = g_dis[n];
    g_agg[t] = b[c] + g_hw[t] * d * d;
}

// edge scatter: agg[dst] += h[src] * norm, vectorized float4 RED
__global__ void k_scatter(const int* __restrict__ ei, int Cout) {
    int CQ = Cout >> 2;
    int t = blockIdx.x * blockDim.x + threadIdx.x;
    if (t >= EE * CQ) return;
    int e = t / CQ, q = t - e * CQ;
    int s = ei[e], d = ei[EE + e];
    float nm = g_norm[e];
    float4 v = *reinterpret_cast<const float4*>(&g_hw[s * Cout + q * 4]);
    red_add_v4(&g_agg[d * Cout + q * 4], v.x * nm, v.y * nm, v.z * nm, v.w * nm);
}

// BN stats over gelu(agg): one block per channel
__global__ void k_stats(int C) {
    int c = blockIdx.x;
    __shared__ float ssum[256], ssq[256];
    float s = 0.f, q = 0.f;
    for (int n = threadIdx.x; n < NN; n += 256) {
        float v = geluf(g_agg[n * C + c]);
        s += v; q += v * v;
    }
    ssum[threadIdx.x] = s; ssq[threadIdx.x] = q;
    __syncthreads();
    for (int o = 128; o > 0; o >>= 1) {
        if (threadIdx.x < o) {
            ssum[threadIdx.x] += ssum[threadIdx.x + o];
            ssq[threadIdx.x]  += ssq[threadIdx.x + o];
        }
        __syncthreads();
    }
    if (threadIdx.x == 0) { g_stats[c] = ssum[0]; g_stats[C + c] = ssq[0]; }
}

// BN apply (recomputes gelu, in place)
__global__ void k_bn(const float* __restrict__ gam, const float* __restrict__ bet, int C) {
    int t = blockIdx.x * blockDim.x + threadIdx.x;
    if (t >= NN * C) return;
    int c = t % C;
    float mu  = g_stats[c] * (1.0f / NN);
    float var = g_stats[C + c] * (1.0f / NN) - mu * mu;
    float v = geluf(g_agg[t]);
    g_agg[t] = gam[c] * (v - mu) * rsqrtf(var + EPSF) + bet[c];
}

// ---------------- pooling + MLP ----------------------------------------------
__global__ void k_cnt(const int* __restrict__ batch) {
    int n = blockIdx.x * blockDim.x + threadIdx.x;
    if (n < NN) atomicAdd(&g_cnt[batch[n]], 1.0f);
}
__global__ void k_pool(const int* __restrict__ batch) {
    int t = blockIdx.x * blockDim.x + threadIdx.x;
    if (t >= NN * 32) return;
    int n = t / 32, q = t - n * 32;
    float4 v = *reinterpret_cast<const float4*>(&g_agg[n * 128 + q * 4]);
    int g = batch[n];
    red_add_v4(&g_pool[g * 128 + q * 4], geluf(v.x), geluf(v.y), geluf(v.z), geluf(v.w));
}
__global__ void k_zfin(const float* __restrict__ yx) {
    int t = blockIdx.x * blockDim.x + threadIdx.x;
    if (t >= GG * 135) return;
    int g = t / 135, j = t - g * 135;
    g_z[t] = (j < 128) ? g_pool[g * 128 + j] / fmaxf(g_cnt[g], 1.0f)
                       : yx[g * 7 + (j - 128)];
}
__global__ void k_mlp(const float* __restrict__ in, const float* __restrict__ W,
                      const float* __restrict__ b, float* __restrict__ out,
                      int Ci, int Co, int act) {
    int t = blockIdx.x * blockDim.x + threadIdx.x;
    if (t >= GG * Co) return;
    int g = t / Co, c = t - g * Co;
    const float* row = in + g * Ci;
    float s = b[c];
    for (int i = 0; i < Ci; ++i) s = fmaf(row[i], W[i * Co + c], s);
    out[t] = act ? (1.0f / (1.0f + expf(-s))) : geluf(s);
}

// ---------------- host -------------------------------------------------------
static inline int gs(int n) { return (n + 255) / 256; }

extern "C" void kernel_launch(void* const* d_in, const int* in_sizes, int n_in,
                              void* d_out, int out_size) {
    const float* x     = (const float*)d_in[0];
    const int*   ei    = (const int*)d_in[1];
    const int*   batch = (const int*)d_in[2];
    const float* yx    = (const float*)d_in[3];
    const float* W[4]  = {(const float*)d_in[4], (const float*)d_in[6],
                          (const float*)d_in[8], (const float*)d_in[10]};
    const float* B[4]  = {(const float*)d_in[5], (const float*)d_in[7],
                          (const float*)d_in[9], (const float*)d_in[11]};
    const float* Gm[3] = {(const float*)d_in[12], (const float*)d_in[14], (const float*)d_in[16]};
    const float* Be[3] = {(const float*)d_in[13], (const float*)d_in[15], (const float*)d_in[17]};
    const float* LW[4] = {(const float*)d_in[18], (const float*)d_in[20],
                          (const float*)d_in[22], (const float*)d_in[24]};
    const float* LB[4] = {(const float*)d_in[19], (const float*)d_in[21],
                          (const float*)d_in[23], (const float*)d_in[25]};

    void *p_dis, *p_agg, *p_pool, *p_cnt, *p_z, *p_m1, *p_m2, *p_m3;
    cudaGetSymbolAddress(&p_dis,  g_dis);
    cudaGetSymbolAddress(&p_agg,  g_agg);
    cudaGetSymbolAddress(&p_pool, g_pool);
    cudaGetSymbolAddress(&p_cnt,  g_cnt);
    cudaGetSymbolAddress(&p_z,    g_z);
    cudaGetSymbolAddress(&p_m1,   g_m1);
    cudaGetSymbolAddress(&p_m2,   g_m2);
    cudaGetSymbolAddress(&p_m3,   g_m3);

    // degree / symmetric norm
    cudaMemsetAsync(p_dis, 0, NN * sizeof(float));
    k_deg <<<gs(EE), 256>>>(ei);
    k_dis <<<gs(NN), 256>>>();
    k_norm<<<gs(EE), 256>>>(ei);

    // 4 GCN layers
    const int Cin[4]  = {1, 16, 32, 64};
    const int Cout[4] = {16, 32, 64, 128};
    const float* inp = x;
    for (int l = 0; l < 4; ++l) {
        int ci = Cin[l], co = Cout[l];
        k_mm     <<<gs(NN * co), 256>>>(inp, W[l], ci, co);
        k_init   <<<gs(NN * co), 256>>>(B[l], co);
        k_scatter<<<gs(EE * (co >> 2)), 256>>>(ei, co);
        if (l < 3) {
            k_stats<<<co, 256>>>(co);
            k_bn   <<<gs(NN * co), 256>>>(Gm[l], Be[l], co);
        }
        inp = (const float*)p_agg;
    }

    // global mean pool (gelu fused here for layer 4) + concat + MLP head
    cudaMemsetAsync(p_pool, 0, GG * 128 * sizeof(float));
    cudaMemsetAsync(p_cnt,  0, GG * sizeof(float));
    k_cnt <<<gs(NN), 256>>>(batch);
    k_pool<<<gs(NN * 32), 256>>>(batch);
    k_zfin<<<gs(GG * 135), 256>>>(yx);

    k_mlp<<<gs(GG * 128), 256>>>((const float*)p_z,  LW[0], LB[0], (float*)p_m1, 135, 128, 0);
    k_mlp<<<gs(GG * 64),  256>>>((const float*)p_m1, LW[1], LB[1], (float*)p_m2, 128, 64, 0);
    k_mlp<<<gs(GG * 32),  256>>>((const float*)p_m2, LW[2], LB[2], (float*)p_m3, 64, 32, 0);
    k_mlp<<<gs(GG * 2),   256>>>((const float*)p_m3, LW[3], LB[3], (float*)d_out, 32, 2, 1);
}

// round 2
// speedup vs baseline: 1.4363x; 1.4363x over previous
#include <cuda_runtime.h>
#include <math.h>

#define NN 50000
#define EE 800000
#define GG 256
#define EPSF 1e-5f

// ---------------- scratch (static device globals; allocation-free) ----------
__device__ __align__(256) float g_hw[NN * 128];    // hw2 = (in @ W) * dis[n]
__device__ __align__(256) float g_agg[NN * 128];   // aggregated / activation
__device__ __align__(256) float g_dis[NN];         // deg^{-1/2}
__device__ __align__(256) int   g_cnt[NN];         // in-degree histogram
__device__ __align__(256) int   g_rowptr[NN + 1];  // CSR row pointers (by dst)
__device__ __align__(256) int   g_cur[NN];         // fill cursors
__device__ __align__(256) int   g_csr[EE];         // src indices bucketed by dst
__device__ __align__(256) float g_stats[256];      // BN sum / sumsq
__device__ __align__(256) float g_pool[GG * 128];
__device__ __align__(256) float g_gcnt[GG];

__device__ __forceinline__ float geluf(float x) {
    return 0.5f * x * (1.0f + erff(x * 0.70710678118654752f));
}

__device__ __forceinline__ void red_add_v4(float* addr, float a, float b, float c, float d) {
    asm volatile("red.global.add.v4.f32 [%0], {%1,%2,%3,%4};"
                 :: "l"(addr), "f"(a), "f"(b), "f"(c), "f"(d)
                 : "memory");
}

// ---------------- CSR build ---------------------------------------------------
__global__ void k_hist(const int* __restrict__ ei) {
    int e = blockIdx.x * blockDim.x + threadIdx.x;
    if (e < EE) atomicAdd(&g_cnt[ei[EE + e]], 1);
}

// single-block scan: rowptr, cursors, dis = rsqrt(deg+1)
__global__ void k_scan() {
    __shared__ int part[1024];
    int tid = threadIdx.x;
    const int CH = (NN + 1023) / 1024;
    int beg = tid * CH, end = min(beg + CH, NN);
    int s = 0;
    for (int i = beg; i < end; ++i) s += g_cnt[i];
    part[tid] = s;
    __syncthreads();
    for (int off = 1; off < 1024; off <<= 1) {
        int v = (tid >= off) ? part[tid - off] : 0;
        __syncthreads();
        part[tid] += v;
        __syncthreads();
    }
    int run = (tid > 0) ? part[tid - 1] : 0;
    for (int i = beg; i < end; ++i) {
        int c = g_cnt[i];
        g_rowptr[i] = run;
        g_cur[i]    = run;
        g_dis[i]    = rsqrtf((float)c + 1.0f);
        run += c;
    }
    if (tid == 1023) g_rowptr[NN] = run;
}

__global__ void k_fill(const int* __restrict__ ei) {
    int e = blockIdx.x * blockDim.x + threadIdx.x;
    if (e < EE) {
        int d = ei[EE + e];
        int pos = atomicAdd(&g_cur[d], 1);
        g_csr[pos] = ei[e];
    }
}

// ---------------- GCN layer pieces --------------------------------------------
// hw2 = (in @ W) * dis[n]
__global__ void k_mm(const float* __restrict__ in, const float* __restrict__ W,
                     int Cin, int Cout) {
    int t = blockIdx.x * blockDim.x + threadIdx.x;
    if (t >= NN * Cout) return;
    int n = t / Cout, c = t - n * Cout;
    const float* row = in + n * Cin;
    float s = 0.f;
    #pragma unroll 4
    for (int i = 0; i < Cin; ++i) s = fmaf(row[i], W[i * Cout + c], s);
    g_hw[t] = s * g_dis[n];
}

// pull gather: agg[n] = b + dis[n] * (hw2[n] + sum over incoming hw2[src])
template<int CQ>
__global__ void k_gather(const float* __restrict__ b) {
    int t = blockIdx.x * blockDim.x + threadIdx.x;
    if (t >= NN * CQ) return;
    int n = t / CQ, q = t - n * CQ;
    const float4* __restrict__ hw = (const float4*)g_hw;
    int rq = n * CQ + q;
    float4 s = hw[rq];
    int j = g_rowptr[n], end = g_rowptr[n + 1];
    for (; j + 4 <= end; j += 4) {
        int s0 = g_csr[j], s1 = g_csr[j+1], s2 = g_csr[j+2], s3 = g_csr[j+3];
        float4 v0 = hw[s0 * CQ + q], v1 = hw[s1 * CQ + q];
        float4 v2 = hw[s2 * CQ + q], v3 = hw[s3 * CQ + q];
        s.x += (v0.x + v1.x) + (v2.x + v3.x);
        s.y += (v0.y + v1.y) + (v2.y + v3.y);
        s.z += (v0.z + v1.z) + (v2.z + v3.z);
        s.w += (v0.w + v1.w) + (v2.w + v3.w);
    }
    for (; j < end; ++j) {
        float4 v = hw[g_csr[j] * CQ + q];
        s.x += v.x; s.y += v.y; s.z += v.z; s.w += v.w;
    }
    float d = g_dis[n];
    float4 bb = *(const float4*)&b[q * 4];
    float4 o;
    o.x = fmaf(d, s.x, bb.x); o.y = fmaf(d, s.y, bb.y);
    o.z = fmaf(d, s.z, bb.z); o.w = fmaf(d, s.w, bb.w);
    ((float4*)g_agg)[rq] = o;
}

// layer-4 gather with gelu + global-mean-pool sum fused (no activation tensor)
__global__ void k_gather_pool(const float* __restrict__ b, const int* __restrict__ batch) {
    const int CQ = 32;
    int t = blockIdx.x * blockDim.x + threadIdx.x;
    if (t >= NN * CQ) return;
    int n = t / CQ, q = t - n * CQ;
    const float4* __restrict__ hw = (const float4*)g_hw;
    float4 s = hw[n * CQ + q];
    int j = g_rowptr[n], end = g_rowptr[n + 1];
    for (; j + 4 <= end; j += 4) {
        int s0 = g_csr[j], s1 = g_csr[j+1], s2 = g_csr[j+2], s3 = g_csr[j+3];
        float4 v0 = hw[s0 * CQ + q], v1 = hw[s1 * CQ + q];
        float4 v2 = hw[s2 * CQ + q], v3 = hw[s3 * CQ + q];
        s.x += (v0.x + v1.x) + (v2.x + v3.x);
        s.y += (v0.y + v1.y) + (v2.y + v3.y);
        s.z += (v0.z + v1.z) + (v2.z + v3.z);
        s.w += (v0.w + v1.w) + (v2.w + v3.w);
    }
    for (; j < end; ++j) {
        float4 v = hw[g_csr[j] * CQ + q];
        s.x += v.x; s.y += v.y; s.z += v.z; s.w += v.w;
    }
    float d = g_dis[n];
    float4 bb = *(const float4*)&b[q * 4];
    int g = batch[n];
    red_add_v4(&g_pool[g * 128 + q * 4],
               geluf(fmaf(d, s.x, bb.x)), geluf(fmaf(d, s.y, bb.y)),
               geluf(fmaf(d, s.z, bb.z)), geluf(fmaf(d, s.w, bb.w)));
}

// gelu in place + BN stats (block smem reduction -> global atomics)
__global__ void k_gstats(int C) {
    extern __shared__ float sh[];   // [2*C]
    int CQ = C >> 2;
    for (int i = threadIdx.x; i < 2 * C; i += blockDim.x) sh[i] = 0.f;
    __syncthreads();
    int total = NN * CQ;
    int stride = gridDim.x * blockDim.x;
    float4* agg = (float4*)g_agg;
    for (int i = blockIdx.x * blockDim.x + threadIdx.x; i < total; i += stride) {
        int q = i % CQ;
        float4 v = agg[i];
        v.x = geluf(v.x); v.y = geluf(v.y); v.z = geluf(v.z); v.w = geluf(v.w);
        agg[i] = v;
        int c0 = q * 4;
        atomicAdd(&sh[c0 + 0], v.x); atomicAdd(&sh[C + c0 + 0], v.x * v.x);
        atomicAdd(&sh[c0 + 1], v.y); atomicAdd(&sh[C + c0 + 1], v.y * v.y);
        atomicAdd(&sh[c0 + 2], v.z); atomicAdd(&sh[C + c0 + 2], v.z * v.z);
        atomicAdd(&sh[c0 + 3], v.w); atomicAdd(&sh[C + c0 + 3], v.w * v.w);
    }
    __syncthreads();
    for (int i = threadIdx.x; i < 2 * C; i += blockDim.x) atomicAdd(&g_stats[i], sh[i]);
}

// BN affine apply (input already gelu'd), in place
__global__ void k_bn(const float* __restrict__ gam, const float* __restrict__ bet, int C) {
    int CQ = C >> 2;
    int t = blockIdx.x * blockDim.x + threadIdx.x;
    if (t >= NN * CQ) return;
    int q = t % CQ;
    float4 v = ((float4*)g_agg)[t];
    float4 o;
    #pragma unroll
    for (int k = 0; k < 4; ++k) {
        int c = q * 4 + k;
        float mu  = g_stats[c] * (1.0f / NN);
        float var = g_stats[C + c] * (1.0f / NN) - mu * mu;
        float sc  = gam[c] * rsqrtf(var + EPSF);
        float shf = bet[c] - mu * sc;
        float x = (&v.x)[k];
        (&o.x)[k] = fmaf(x, sc, shf);
    }
    ((float4*)g_agg)[t] = o;
}

// ---------------- pooling counts + fused MLP head -----------------------------
__global__ void k_gcnt(const int* __restrict__ batch) {
    int n = blockIdx.x * blockDim.x + threadIdx.x;
    if (n < NN) atomicAdd(&g_gcnt[batch[n]], 1.0f);
}

__global__ void k_head(const float* __restrict__ yx,
                       const float* __restrict__ lw1, const float* __restrict__ lb1,
                       const float* __restrict__ lw2, const float* __restrict__ lb2,
                       const float* __restrict__ lw3, const float* __restrict__ lb3,
                       const float* __restrict__ lw4, const float* __restrict__ lb4,
                       float* __restrict__ out) {
    int g = blockIdx.x, tid = threadIdx.x;
    __shared__ float z[136], a1[128], a2[64], a3[32];
    float inv = 1.0f / fmaxf(g_gcnt[g], 1.0f);
    for (int j = tid; j < 135; j += 128)
        z[j] = (j < 128) ? g_pool[g * 128 + j] * inv : yx[g * 7 + (j - 128)];
    __syncthreads();
    {
        float s = lb1[tid];
        #pragma unroll 5
        for (int i = 0; i < 135; ++i) s = fmaf(z[i], lw1[i * 128 + tid], s);
        a1[tid] = geluf(s);
    }
    __syncthreads();
    if (tid < 64) {
        float s = lb2[tid];
        #pragma unroll 8
        for (int i = 0; i < 128; ++i) s = fmaf(a1[i], lw2[i * 64 + tid], s);
        a2[tid] = geluf(s);
    }
    __syncthreads();
    if (tid < 32) {
        float s = lb3[tid];
        #pragma unroll 8
        for (int i = 0; i < 64; ++i) s = fmaf(a2[i], lw3[i * 32 + tid], s);
        a3[tid] = geluf(s);
    }
    __syncthreads();
    if (tid < 2) {
        float s = lb4[tid];
        #pragma unroll
        for (int i = 0; i < 32; ++i) s = fmaf(a3[i], lw4[i * 2 + tid], s);
        out[g * 2 + tid] = 1.0f / (1.0f + expf(-s));
    }
}

// ---------------- host ---------------------------------------------------------
static inline int gs(int n) { return (n + 255) / 256; }

extern "C" void kernel_launch(void* const* d_in, const int* in_sizes, int n_in,
                              void* d_out, int out_size) {
    const float* x     = (const float*)d_in[0];
    const int*   ei    = (const int*)d_in[1];
    const int*   batch = (const int*)d_in[2];
    const float* yx    = (const float*)d_in[3];
    const float* W[4]  = {(const float*)d_in[4], (const float*)d_in[6],
                          (const float*)d_in[8], (const float*)d_in[10]};
    const float* B[4]  = {(const float*)d_in[5], (const float*)d_in[7],
                          (const float*)d_in[9], (const float*)d_in[11]};
    const float* Gm[3] = {(const float*)d_in[12], (const float*)d_in[14], (const float*)d_in[16]};
    const float* Be[3] = {(const float*)d_in[13], (const float*)d_in[15], (const float*)d_in[17]};
    const float* LW[4] = {(const float*)d_in[18], (const float*)d_in[20],
                          (const float*)d_in[22], (const float*)d_in[24]};
    const float* LB[4] = {(const float*)d_in[19], (const float*)d_in[21],
                          (const float*)d_in[23], (const float*)d_in[25]};

    void *p_cnt, *p_agg, *p_pool, *p_gcnt, *p_stats;
    cudaGetSymbolAddress(&p_cnt,   g_cnt);
    cudaGetSymbolAddress(&p_agg,   g_agg);
    cudaGetSymbolAddress(&p_pool,  g_pool);
    cudaGetSymbolAddress(&p_gcnt,  g_gcnt);
    cudaGetSymbolAddress(&p_stats, g_stats);

    // CSR build (bucket edges by dst) + degree norm
    cudaMemsetAsync(p_cnt,  0, NN * sizeof(int));
    cudaMemsetAsync(p_pool, 0, GG * 128 * sizeof(float));
    cudaMemsetAsync(p_gcnt, 0, GG * sizeof(float));
    k_hist<<<gs(EE), 256>>>(ei);
    k_scan<<<1, 1024>>>();
    k_fill<<<gs(EE), 256>>>(ei);
    k_gcnt<<<gs(NN), 256>>>(batch);

    const int Cin[4]  = {1, 16, 32, 64};
    const int Cout[4] = {16, 32, 64, 128};
    const float* inp = x;
    for (int l = 0; l < 4; ++l) {
        int ci = Cin[l], co = Cout[l], cq = co >> 2;
        k_mm<<<gs(NN * co), 256>>>(inp, W[l], ci, co);
        if (l == 0)      k_gather<4> <<<gs(NN * cq), 256>>>(B[l]);
        else if (l == 1) k_gather<8> <<<gs(NN * cq), 256>>>(B[l]);
        else if (l == 2) k_gather<16><<<gs(NN * cq), 256>>>(B[l]);
        else             k_gather_pool<<<gs(NN * 32), 256>>>(B[l], batch);
        if (l < 3) {
            cudaMemsetAsync(p_stats, 0, 2 * co * sizeof(float));
            k_gstats<<<592, 256, 2 * co * sizeof(float)>>>(co);
            k_bn<<<gs(NN * cq), 256>>>(Gm[l], Be[l], co);
        }
        inp = (const float*)p_agg;
    }

    k_head<<<GG, 128>>>(yx, LW[0], LB[0], LW[1], LB[1],
                        LW[2], LB[2], LW[3], LB[3], (float*)d_out);
}

// round 3
// speedup vs baseline: 2.1615x; 1.5049x over previous
#include <cuda_runtime.h>
#include <math.h>

#define NN 50000
#define EE 800000
#define GG 256
#define EPSF 1e-5f
#define SCAN_B 196   // ceil(50000/256)

// ---------------- scratch ----------------------------------------------------
__device__ __align__(256) float g_hw[NN * 128];     // (in @ W') * dis
__device__ __align__(256) float g_agg[NN * 128];    // activations
__device__ __align__(256) float g_dis[NN];          // deg^{-1/2}
__device__ __align__(256) float g_rs[NN];           // dis[n]*(dis[n]+sum dis[src])
__device__ __align__(256) int   g_cnt[NN];          // in-degree histogram
__device__ __align__(256) int   g_rowptr[NN + 1];
__device__ __align__(256) int   g_cur[NN];
__device__ __align__(256) int   g_csr[EE];
__device__ __align__(256) int   g_bsum[SCAN_B];     // scan partials
__device__ __align__(256) float g_stats[512];       // [l*128 .. l*128+2C) + badd @384
__device__ __align__(256) float g_wf[64 * 128];     // folded weights
__device__ __align__(256) float g_pool[GG * 128];

__device__ __forceinline__ float geluf(float x) {
    return 0.5f * x * (1.0f + erff(x * 0.70710678118654752f));
}
__device__ __forceinline__ void red_add_v4(float* addr, float a, float b, float c, float d) {
    asm volatile("red.global.add.v4.f32 [%0], {%1,%2,%3,%4};"
                 :: "l"(addr), "f"(a), "f"(b), "f"(c), "f"(d) : "memory");
}

// ---------------- CSR build ---------------------------------------------------
__global__ void k_hist(const int* __restrict__ ei) {
    int e = blockIdx.x * blockDim.x + threadIdx.x;
    if (e < EE) atomicAdd(&g_cnt[ei[EE + e]], 1);
}
__global__ void k_scanA() {   // per-block sums of g_cnt
    __shared__ int sh[256];
    int i = blockIdx.x * 256 + threadIdx.x;
    sh[threadIdx.x] = (i < NN) ? g_cnt[i] : 0;
    __syncthreads();
    for (int o = 128; o > 0; o >>= 1) {
        if (threadIdx.x < o) sh[threadIdx.x] += sh[threadIdx.x + o];
        __syncthreads();
    }
    if (threadIdx.x == 0) g_bsum[blockIdx.x] = sh[0];
}
__global__ void k_scanB() {   // exclusive scan of SCAN_B block sums (1 block)
    __shared__ int sh[256];
    int t = threadIdx.x;
    int v = (t < SCAN_B) ? g_bsum[t] : 0;
    sh[t] = v;
    __syncthreads();
    for (int o = 1; o < 256; o <<= 1) {
        int u = (t >= o) ? sh[t - o] : 0;
        __syncthreads();
        sh[t] += u;
        __syncthreads();
    }
    if (t < SCAN_B) g_bsum[t] = sh[t] - v;
    if (t == 0) g_rowptr[NN] = EE;
}
__global__ void k_scanC() {   // rowptr / cursors / dis
    __shared__ int sh[256];
    int i = blockIdx.x * 256 + threadIdx.x;
    int t = threadIdx.x;
    int c = (i < NN) ? g_cnt[i] : 0;
    sh[t] = c;
    __syncthreads();
    for (int o = 1; o < 256; o <<= 1) {
        int u = (t >= o) ? sh[t - o] : 0;
        __syncthreads();
        sh[t] += u;
        __syncthreads();
    }
    if (i < NN) {
        int rp = g_bsum[blockIdx.x] + sh[t] - c;
        g_rowptr[i] = rp;
        g_cur[i]    = rp;
        g_dis[i]    = rsqrtf((float)c + 1.0f);
    }
}
__global__ void k_fill(const int* __restrict__ ei) {
    int e = blockIdx.x * blockDim.x + threadIdx.x;
    if (e < EE) {
        int pos = atomicAdd(&g_cur[ei[EE + e]], 1);
        g_csr[pos] = ei[e];
    }
}
__global__ void k_rs() {      // rs[n] = dis[n]*(dis[n] + sum dis[src])
    int n = blockIdx.x * blockDim.x + threadIdx.x;
    if (n >= NN) return;
    int j = g_rowptr[n], end = g_rowptr[n + 1];
    float s = g_dis[n];
    float s0 = 0.f, s1 = 0.f, s2 = 0.f, s3 = 0.f;
    for (; j + 4 <= end; j += 4) {
        s0 += g_dis[g_csr[j]];   s1 += g_dis[g_csr[j+1]];
        s2 += g_dis[g_csr[j+2]]; s3 += g_dis[g_csr[j+3]];
    }
    for (; j < end; ++j) s0 += g_dis[g_csr[j]];
    g_rs[n] = g_dis[n] * (s + (s0 + s1) + (s2 + s3));
}

// ---------------- BN fold: W' = sc*W, badd = shf@W -----------------------------
__global__ void k_fold(const float* __restrict__ gam, const float* __restrict__ bet,
                       const float* __restrict__ W, int Cin, int Cout,
                       const float* __restrict__ stats) {
    __shared__ float sc[64], shf[64];
    int t = threadIdx.x;
    if (t < Cin) {
        float mu  = stats[t] * (1.0f / NN);
        float var = stats[Cin + t] * (1.0f / NN) - mu * mu;
        float s = gam[t] * rsqrtf(var + EPSF);
        sc[t] = s;
        shf[t] = bet[t] - mu * s;
    }
    __syncthreads();
    if (t < Cout) {
        float ba = 0.f;
        for (int i = 0; i < Cin; ++i) {
            float w = W[i * Cout + t];
            g_wf[i * Cout + t] = sc[i] * w;
            ba = fmaf(shf[i], w, ba);
        }
        g_stats[384 + t] = ba;   // badd
    }
}

// ---------------- GCN layer pieces ---------------------------------------------
__global__ void k_mm(const float* __restrict__ in, const float* __restrict__ W,
                     int Cin, int Cout) {
    int t = blockIdx.x * blockDim.x + threadIdx.x;
    if (t >= NN * Cout) return;
    int n = t / Cout, c = t - n * Cout;
    const float* row = in + n * Cin;
    float s = 0.f;
    #pragma unroll 4
    for (int i = 0; i < Cin; ++i) s = fmaf(row[i], W[i * Cout + c], s);
    g_hw[t] = s * g_dis[n];
}

// gather + bias(+badd*rs) + gelu + BN-stat accumulation (layers 1-3)
template<int CQ>
__global__ void k_gather(const float* __restrict__ b, float* __restrict__ statsOut) {
    const int C = 4 * CQ;
    __shared__ float sh[2 * C];
    int tid = threadIdx.x;
    int t = blockIdx.x * 256 + tid;
    bool valid = t < NN * CQ;
    for (int i = tid; i < 2 * C; i += 256) sh[i] = 0.f;
    __syncthreads();

    float4 r = make_float4(0.f, 0.f, 0.f, 0.f);
    if (valid) {
        int n = t / CQ, q = t - n * CQ;
        const float4* __restrict__ hw = (const float4*)g_hw;
        float4 s = hw[n * CQ + q];
        int j = g_rowptr[n], end = g_rowptr[n + 1];
        for (; j + 4 <= end; j += 4) {
            int s0 = g_csr[j], s1 = g_csr[j+1], s2 = g_csr[j+2], s3 = g_csr[j+3];
            float4 v0 = hw[s0 * CQ + q], v1 = hw[s1 * CQ + q];
            float4 v2 = hw[s2 * CQ + q], v3 = hw[s3 * CQ + q];
            s.x += (v0.x + v1.x) + (v2.x + v3.x);
            s.y += (v0.y + v1.y) + (v2.y + v3.y);
            s.z += (v0.z + v1.z) + (v2.z + v3.z);
            s.w += (v0.w + v1.w) + (v2.w + v3.w);
        }
        for (; j < end; ++j) {
            float4 v = hw[g_csr[j] * CQ + q];
            s.x += v.x; s.y += v.y; s.z += v.z; s.w += v.w;
        }
        float d = g_dis[n], rs = g_rs[n];
        float4 bb = *(const float4*)&b[q * 4];
        float4 ba = *(const float4*)&g_stats[384 + q * 4];
        r.x = geluf(fmaf(d, s.x, fmaf(ba.x, rs, bb.x)));
        r.y = geluf(fmaf(d, s.y, fmaf(ba.y, rs, bb.y)));
        r.z = geluf(fmaf(d, s.z, fmaf(ba.z, rs, bb.z)));
        r.w = geluf(fmaf(d, s.w, fmaf(ba.w, rs, bb.w)));
        ((float4*)g_agg)[n * CQ + q] = r;
    }
    // stats: reduce lanes sharing the same channel quad, then smem, then global
    float4 r2 = make_float4(r.x * r.x, r.y * r.y, r.z * r.z, r.w * r.w);
    #pragma unroll
    for (int off = CQ; off < 32; off <<= 1) {
        r.x  += __shfl_down_sync(0xffffffffu, r.x,  off);
        r.y  += __shfl_down_sync(0xffffffffu, r.y,  off);
        r.z  += __shfl_down_sync(0xffffffffu, r.z,  off);
        r.w  += __shfl_down_sync(0xffffffffu, r.w,  off);
        r2.x += __shfl_down_sync(0xffffffffu, r2.x, off);
        r2.y += __shfl_down_sync(0xffffffffu, r2.y, off);
        r2.z += __shfl_down_sync(0xffffffffu, r2.z, off);
        r2.w += __shfl_down_sync(0xffffffffu, r2.w, off);
    }
    if ((tid & 31) < CQ) {
        int c0 = (tid % CQ) * 4;
        atomicAdd(&sh[c0 + 0], r.x);  atomicAdd(&sh[C + c0 + 0], r2.x);
        atomicAdd(&sh[c0 + 1], r.y);  atomicAdd(&sh[C + c0 + 1], r2.y);
        atomicAdd(&sh[c0 + 2], r.z);  atomicAdd(&sh[C + c0 + 2], r2.z);
        atomicAdd(&sh[c0 + 3], r.w);  atomicAdd(&sh[C + c0 + 3], r2.w);
    }
    __syncthreads();
    for (int i = tid; i < 2 * C; i += 256) atomicAdd(&statsOut[i], sh[i]);
}

// layer-4 gather: bias(+badd*rs) + gelu + mean-pool sum fused
__global__ void k_gather_pool(const float* __restrict__ b, const int* __restrict__ batch) {
    const int CQ = 32;
    int t = blockIdx.x * blockDim.x + threadIdx.x;
    if (t >= NN * CQ) return;
    int n = t / CQ, q = t - n * CQ;
    const float4* __restrict__ hw = (const float4*)g_hw;
    float4 s = hw[n * CQ + q];
    int j = g_rowptr[n], end = g_rowptr[n + 1];
    for (; j + 4 <= end; j += 4) {
        int s0 = g_csr[j], s1 = g_csr[j+1], s2 = g_csr[j+2], s3 = g_csr[j+3];
        float4 v0 = hw[s0 * CQ + q], v1 = hw[s1 * CQ + q];
        float4 v2 = hw[s2 * CQ + q], v3 = hw[s3 * CQ + q];
        s.x += (v0.x + v1.x) + (v2.x + v3.x);
        s.y += (v0.y + v1.y) + (v2.y + v3.y);
        s.z += (v0.z + v1.z) + (v2.z + v3.z);
        s.w += (v0.w + v1.w) + (v2.w + v3.w);
    }
    for (; j < end; ++j) {
        float4 v = hw[g_csr[j] * CQ + q];
        s.x += v.x; s.y += v.y; s.z += v.z; s.w += v.w;
    }
    float d = g_dis[n], rs = g_rs[n];
    float4 bb = *(const float4*)&b[q * 4];
    float4 ba = *(const float4*)&g_stats[384 + q * 4];
    int g = batch[n];
    red_add_v4(&g_pool[g * 128 + q * 4],
               geluf(fmaf(d, s.x, fmaf(ba.x, rs, bb.x))),
               geluf(fmaf(d, s.y, fmaf(ba.y, rs, bb.y))),
               geluf(fmaf(d, s.z, fmaf(ba.z, rs, bb.z))),
               geluf(fmaf(d, s.w, fmaf(ba.w, rs, bb.w))));
}

// ---------------- fused MLP head (graph count via binary search) ----------------
__global__ void k_head(const int* __restrict__ batch, const float* __restrict__ yx,
                       const float* __restrict__ lw1, const float* __restrict__ lb1,
                       const float* __restrict__ lw2, const float* __restrict__ lb2,
                       const float* __restrict__ lw3, const float* __restrict__ lb3,
                       const float* __restrict__ lw4, const float* __restrict__ lb4,
                       float* __restrict__ out) {
    int g = blockIdx.x, tid = threadIdx.x;
    __shared__ float z[136], a1[128], a2[64], a3[32];
    __shared__ int bounds[2];
    if (tid < 2) {   // lower_bound(batch, g + tid) over sorted batch
        int key = g + tid;
        int lo = 0, hi = NN;
        while (lo < hi) {
            int mid = (lo + hi) >> 1;
            if (batch[mid] < key) lo = mid + 1; else hi = mid;
        }
        bounds[tid] = lo;
    }
    __syncthreads();
    float inv = 1.0f / fmaxf((float)(bounds[1] - bounds[0]), 1.0f);
    for (int j = tid; j < 135; j += 128)
        z[j] = (j < 128) ? g_pool[g * 128 + j] * inv : yx[g * 7 + (j - 128)];
    __syncthreads();
    {
        float s = lb1[tid];
        #pragma unroll 5
        for (int i = 0; i < 135; ++i) s = fmaf(z[i], lw1[i * 128 + tid], s);
        a1[tid] = geluf(s);
    }
    __syncthreads();
    if (tid < 64) {
        float s = lb2[tid];
        #pragma unroll 8
        for (int i = 0; i < 128; ++i) s = fmaf(a1[i], lw2[i * 64 + tid], s);
        a2[tid] = geluf(s);
    }
    __syncthreads();
    if (tid < 32) {
        float s = lb3[tid];
        #pragma unroll 8
        for (int i = 0; i < 64; ++i) s = fmaf(a2[i], lw3[i * 32 + tid], s);
        a3[tid] = geluf(s);
    }
    __syncthreads();
    if (tid < 2) {
        float s = lb4[tid];
        #pragma unroll
        for (int i = 0; i < 32; ++i) s = fmaf(a3[i], lw4[i * 2 + tid], s);
        out[g * 2 + tid] = 1.0f / (1.0f + expf(-s));
    }
}

// ---------------- host -----------------------------------------------------------
static inline int gs(int n) { return (n + 255) / 256; }

extern "C" void kernel_launch(void* const* d_in, const int* in_sizes, int n_in,
                              void* d_out, int out_size) {
    const float* x     = (const float*)d_in[0];
    const int*   ei    = (const int*)d_in[1];
    const int*   batch = (const int*)d_in[2];
    const float* yx    = (const float*)d_in[3];
    const float* W[4]  = {(const float*)d_in[4], (const float*)d_in[6],
                          (const float*)d_in[8], (const float*)d_in[10]};
    const float* B[4]  = {(const float*)d_in[5], (const float*)d_in[7],
                          (const float*)d_in[9], (const float*)d_in[11]};
    const float* Gm[3] = {(const float*)d_in[12], (const float*)d_in[14], (const float*)d_in[16]};
    const float* Be[3] = {(const float*)d_in[13], (const float*)d_in[15], (const float*)d_in[17]};
    const float* LW[4] = {(const float*)d_in[18], (const float*)d_in[20],
                          (const float*)d_in[22], (const float*)d_in[24]};
    const float* LB[4] = {(const float*)d_in[19], (const float*)d_in[21],
                          (const float*)d_in[23], (const float*)d_in[25]};

    void *p_cnt, *p_agg, *p_pool, *p_stats, *p_wf;
    cudaGetSymbolAddress(&p_cnt,   g_cnt);
    cudaGetSymbolAddress(&p_agg,   g_agg);
    cudaGetSymbolAddress(&p_pool,  g_pool);
    cudaGetSymbolAddress(&p_stats, g_stats);
    cudaGetSymbolAddress(&p_wf,    g_wf);
    float* stats = (float*)p_stats;

    cudaMemsetAsync(p_cnt,   0, NN * sizeof(int));
    cudaMemsetAsync(p_pool,  0, GG * 128 * sizeof(float));
    cudaMemsetAsync(p_stats, 0, 512 * sizeof(float));   // stats + badd

    k_hist <<<gs(EE), 256>>>(ei);
    k_scanA<<<SCAN_B, 256>>>();
    k_scanB<<<1, 256>>>();
    k_scanC<<<SCAN_B, 256>>>();
    k_fill <<<gs(EE), 256>>>(ei);
    k_rs   <<<gs(NN), 256>>>();

    const int Cin[4]  = {1, 16, 32, 64};
    const int Cout[4] = {16, 32, 64, 128};
    const float* inp = x;
    for (int l = 0; l < 4; ++l) {
        int ci = Cin[l], co = Cout[l], cq = co >> 2;
        const float* Wl = W[l];
        if (l > 0) {   // fold previous BN into this layer's weights
            k_fold<<<1, 128>>>(Gm[l-1], Be[l-1], W[l], ci, co, stats + (l-1) * 128);
            Wl = (const float*)p_wf;
        }
        k_mm<<<gs(NN * co), 256>>>(inp, Wl, ci, co);
        if (l == 0)      k_gather<4> <<<gs(NN * cq), 256>>>(B[l], stats + 0);
        else if (l == 1) k_gather<8> <<<gs(NN * cq), 256>>>(B[l], stats + 128);
        else if (l == 2) k_gather<16><<<gs(NN * cq), 256>>>(B[l], stats + 256);
        else             k_gather_pool<<<gs(NN * 32), 256>>>(B[l], batch);
        inp = (const float*)p_agg;
    }

    k_head<<<GG, 128>>>(batch, yx, LW[0], LB[0], LW[1], LB[1],
                        LW[2], LB[2], LW[3], LB[3], (float*)d_out);
}